// round 8
// baseline (speedup 1.0000x reference)
#include <cuda_runtime.h>
#include <cuda_fp16.h>
#include <cstdint>

#define WSIZE 9216
#define PSTRIDE 9248

#define XPITCH 20                        // words/pixel: 16 data + 4 pad (conflict-free, proven R5)
#define XROWW  (130 * XPITCH)            // 2600
#define XT_WORDS (6 * XROWW)             // 15600
#define SMEM_BYTES (XT_WORDS * 4)        // 62400 -> 3 CTAs/SM

#define WB_WORDS 4608                    // per batch: 18 steps x 2 quads x 32 lanes x 4 words

// weights in fragment-major order, fp16 pairs:
// word i = ((st*2+q)*32 + lane)*4 + w ; nt = q*2+(w>>1), half = w&1
// -> f = nt*8 + (lane>>2), kword = st*8 + (lane&3) + half*4, value = (k=2*kword, 2*kword+1)
__device__ uint32_t gWB[32 * WB_WORDS];

__device__ __forceinline__ uint32_t pack2(float a, float b) {
    __half2 h = __floats2half2_rn(a, b);
    return *(uint32_t*)&h;
}
__device__ __forceinline__ void mma_f16(float& c0, float& c1, float& c2, float& c3,
                                        uint32_t a0, uint32_t a1, uint32_t a2, uint32_t a3,
                                        uint32_t b0, uint32_t b1) {
    asm volatile(
        "mma.sync.aligned.m16n8k16.row.col.f32.f16.f16.f32 "
        "{%0,%1,%2,%3}, {%4,%5,%6,%7}, {%8,%9}, {%0,%1,%2,%3};"
        : "+f"(c0), "+f"(c1), "+f"(c2), "+f"(c3)
        : "r"(a0), "r"(a1), "r"(a2), "r"(a3), "r"(b0), "r"(b1));
}

// ---- precompute: weights -> fragment-major fp16, once per batch ----
__global__ __launch_bounds__(256)
void wprep(const float* __restrict__ params) {
    __shared__ float s[288 * 33];
    const int b = blockIdx.x;
    const int tid = threadIdx.x;
    const float* pw = params + (long)b * PSTRIDE;
    #pragma unroll
    for (int i = tid; i < 9216; i += 256) {
        int k = i >> 5, f = i & 31;
        s[k * 33 + f] = pw[i];
    }
    __syncthreads();
    uint32_t* gw = gWB + b * WB_WORDS;
    #pragma unroll
    for (int i = tid; i < WB_WORDS; i += 256) {
        int w  = i & 3;
        int l  = (i >> 2) & 31;
        int q  = (i >> 7) & 1;
        int st = i >> 8;
        int nt = q * 2 + (w >> 1);
        int half = w & 1;
        int f  = nt * 8 + (l >> 2);
        int kw = st * 8 + (l & 3) + half * 4;      // word index along k
        gw[i] = pack2(s[(2 * kw) * 33 + f], s[(2 * kw + 1) * 33 + f]);
    }
}

__global__ __launch_bounds__(256, 3)
void conv_mma_f16(const float* __restrict__ x, const float* __restrict__ params,
                  float* __restrict__ out) {
    extern __shared__ uint32_t smem[];
    uint32_t* sX = smem;                 // [row 0..5][pix 0..129][XPITCH], fp16 k-major

    const int tid = threadIdx.x;
    const int wid = tid >> 5;
    const int lid = tid & 31;
    const int g   = lid >> 2;
    const int t   = lid & 3;
    const int y0  = blockIdx.x * 4;      // 4 output rows per CTA
    const int b   = blockIdx.y;

    // ---- build X tile: input rows y0-1 .. y0+4, pixels -1..128 at 0..129 ----
    const float* xb = x + (long)b * (128 * 128 * 32);
    #pragma unroll
    for (int it = 0; it < 24; it++) {
        int idx = tid + it * 256;        // 0..6143
        int c4  = idx & 7;
        int px  = (idx >> 3) & 127;
        int row = idx >> 10;             // 0..5
        int gy  = y0 + row - 1;
        uint2 v = make_uint2(0u, 0u);
        if ((unsigned)gy < 128u) {
            float4 s = *(const float4*)(xb + ((gy * 128 + px) * 32 + c4 * 4));
            v.x = pack2(s.x, s.y);
            v.y = pack2(s.z, s.w);
        }
        *(uint2*)(sX + row * XROWW + (px + 1) * XPITCH + c4 * 2) = v;
    }
    if (tid < 192) {
        int row = tid >> 5, rem = tid & 31;
        int pix = (rem >> 4) ? 129 : 0;
        sX[row * XROWW + pix * XPITCH + (rem & 15)] = 0u;
    }
    __syncthreads();

    const int yl = wid >> 1;             // local output row 0..3
    const int m0 = (wid & 1) * 64;       // 64 px per warp

    const uint4* wq = (const uint4*)(gWB + b * WB_WORDS);

    float acc[4][4][4];
    #pragma unroll
    for (int mi = 0; mi < 4; mi++)
        #pragma unroll
        for (int nt = 0; nt < 4; nt++)
            #pragma unroll
            for (int j = 0; j < 4; j++) acc[mi][nt][j] = 0.f;

    #pragma unroll
    for (int kh = 0; kh < 3; kh++) {
        const uint32_t* xr = sX + (yl + kh) * XROWW;
        #pragma unroll
        for (int kw = 0; kw < 3; kw++) {
            #pragma unroll
            for (int c16 = 0; c16 < 2; c16++) {
                const int st = kh * 6 + kw * 2 + c16;

                // B fragments: two coalesced LDG.128 from L1-resident gWB
                uint4 B0 = __ldg(wq + (st * 2 + 0) * 32 + lid);
                uint4 B1 = __ldg(wq + (st * 2 + 1) * 32 + lid);

                #pragma unroll
                for (int mi = 0; mi < 4; mi++) {
                    const uint32_t* ap = xr + (m0 + mi * 16 + g + kw) * XPITCH
                                            + c16 * 8 + t;
                    uint32_t a0 = ap[0];
                    uint32_t a1 = ap[8 * XPITCH];
                    uint32_t a2 = ap[4];
                    uint32_t a3 = ap[8 * XPITCH + 4];
                    mma_f16(acc[mi][0][0], acc[mi][0][1], acc[mi][0][2], acc[mi][0][3],
                            a0, a1, a2, a3, B0.x, B0.y);
                    mma_f16(acc[mi][1][0], acc[mi][1][1], acc[mi][1][2], acc[mi][1][3],
                            a0, a1, a2, a3, B0.z, B0.w);
                    mma_f16(acc[mi][2][0], acc[mi][2][1], acc[mi][2][2], acc[mi][2][3],
                            a0, a1, a2, a3, B1.x, B1.y);
                    mma_f16(acc[mi][3][0], acc[mi][3][1], acc[mi][3][2], acc[mi][3][3],
                            a0, a1, a2, a3, B1.z, B1.w);
                }
            }
        }
    }

    // ---- epilogue: + bias, store ----
    const float* bp = params + (long)b * PSTRIDE + WSIZE;
    float* ob = out + ((long)(b * 128 + y0 + yl)) * 128 * 32;
    #pragma unroll
    for (int nt = 0; nt < 4; nt++) {
        int f = nt * 8 + t * 2;
        float2 bias = *(const float2*)(bp + f);
        #pragma unroll
        for (int mi = 0; mi < 4; mi++) {
            int px = m0 + mi * 16 + g;
            float2 o0, o1;
            o0.x = acc[mi][nt][0] + bias.x;
            o0.y = acc[mi][nt][1] + bias.y;
            o1.x = acc[mi][nt][2] + bias.x;
            o1.y = acc[mi][nt][3] + bias.y;
            *(float2*)(ob + px * 32 + f)       = o0;
            *(float2*)(ob + (px + 8) * 32 + f) = o1;
        }
    }
}

extern "C" void kernel_launch(void* const* d_in, const int* in_sizes, int n_in,
                              void* d_out, int out_size) {
    const float* x      = (const float*)d_in[0];
    const float* params = (const float*)d_in[1];
    float* out          = (float*)d_out;

    wprep<<<32, 256>>>(params);

    cudaFuncSetAttribute(conv_mma_f16, cudaFuncAttributeMaxDynamicSharedMemorySize, SMEM_BYTES);
    dim3 grid(32, 32);   // (row-quad, batch)
    conv_mma_f16<<<grid, 256, SMEM_BYTES>>>(x, params, out);
}

// round 9
// speedup vs baseline: 1.0703x; 1.0703x over previous
#include <cuda_runtime.h>
#include <cuda_fp16.h>
#include <cstdint>

#define WSIZE 9216
#define PSTRIDE 9248

#define XPITCH 16                        // words/pixel, XOR-swizzled (no pad)
#define XROWW  (130 * XPITCH)            // 2080
#define XT_WORDS (6 * XROWW)             // 12480
#define WPITCH 148                       // words/filter: 144 data + 4 pad (proven conflict-free)
#define WT_WORDS (32 * WPITCH)           // 4736
#define SMEM_BYTES ((XT_WORDS + WT_WORDS) * 4)   // 68864 -> 3 CTAs/SM

// swizzle: word w of pixel px stored at w ^ (((px>>1)&3)<<2)
#define SWZ(px) ((((px) >> 1) & 3) << 2)

// precomputed W^T fp16, plain k-major: [b][f][WPITCH words], word w = (k=2w,2w+1)
__device__ uint32_t gWT[32 * WT_WORDS];

__device__ __forceinline__ uint32_t pack2(float a, float b) {
    __half2 h = __floats2half2_rn(a, b);
    return *(uint32_t*)&h;
}
__device__ __forceinline__ void mma_f16(float& c0, float& c1, float& c2, float& c3,
                                        uint32_t a0, uint32_t a1, uint32_t a2, uint32_t a3,
                                        uint32_t b0, uint32_t b1) {
    asm volatile(
        "mma.sync.aligned.m16n8k16.row.col.f32.f16.f16.f32 "
        "{%0,%1,%2,%3}, {%4,%5,%6,%7}, {%8,%9}, {%0,%1,%2,%3};"
        : "+f"(c0), "+f"(c1), "+f"(c2), "+f"(c3)
        : "r"(a0), "r"(a1), "r"(a2), "r"(a3), "r"(b0), "r"(b1));
}

// ---- precompute W^T fp16 (plain k-major), 3 blocks per batch ----
__global__ __launch_bounds__(256)
void wprep(const float* __restrict__ params) {
    __shared__ float s[96 * 33];
    const int b  = blockIdx.x / 3;
    const int kc = blockIdx.x % 3;
    const int tid = threadIdx.x;
    const float* pw = params + (long)b * PSTRIDE + kc * 96 * 32;
    #pragma unroll
    for (int i = tid; i < 96 * 32; i += 256) {
        int k = i >> 5, f = i & 31;
        s[k * 33 + f] = pw[i];
    }
    __syncthreads();
    uint32_t* gw = gWT + b * WT_WORDS + kc * 48;
    #pragma unroll
    for (int i = tid; i < 32 * 48; i += 256) {
        int f = i / 48, n = i - f * 48;
        gw[f * WPITCH + n] = pack2(s[(2 * n) * 33 + f], s[(2 * n + 1) * 33 + f]);
    }
}

__global__ __launch_bounds__(256, 3)
void conv_mma_f16(const float* __restrict__ x, const float* __restrict__ params,
                  float* __restrict__ out) {
    extern __shared__ uint32_t smem[];
    uint32_t* sX = smem;                 // [row 0..5][pix 0..129][16 swizzled words]
    uint32_t* sW = smem + XT_WORDS;      // [f][WPITCH], plain k-major

    const int tid = threadIdx.x;
    const int wid = tid >> 5;
    const int lid = tid & 31;
    const int g   = lid >> 2;
    const int t   = lid & 3;
    const int y0  = blockIdx.x * 4;
    const int b   = blockIdx.y;

    // ---- copy precomputed W^T (uint4 memcpy) ----
    const uint4* gw4 = (const uint4*)(gWT + b * WT_WORDS);
    #pragma unroll
    for (int it = 0; it < 5; it++) {
        int idx = tid + it * 256;
        if (idx < WT_WORDS / 4) ((uint4*)sW)[idx] = gw4[idx];
    }

    // ---- build X tile: rows y0-1 .. y0+4, pixels -1..128 at 0..129, fp16 swizzled ----
    const float* xb = x + (long)b * (128 * 128 * 32);
    #pragma unroll
    for (int it = 0; it < 24; it++) {
        int idx = tid + it * 256;        // 0..6143
        int c4  = idx & 7;
        int px  = (idx >> 3) & 127;
        int row = idx >> 10;
        int gy  = y0 + row - 1;
        uint2 v = make_uint2(0u, 0u);
        if ((unsigned)gy < 128u) {
            float4 s = *(const float4*)(xb + ((gy * 128 + px) * 32 + c4 * 4));
            v.x = pack2(s.x, s.y);
            v.y = pack2(s.z, s.w);
        }
        const int pix = px + 1;
        // 2*c4 is even, swizzle flips bits 2-3 only -> pair stays 8B-aligned
        *(uint2*)(sX + row * XROWW + pix * XPITCH + ((2 * c4) ^ SWZ(pix))) = v;
    }
    if (tid < 192) {
        int row = tid >> 5, rem = tid & 31;
        int pix = (rem >> 4) ? 129 : 0;
        sX[row * XROWW + pix * XPITCH + (rem & 15)] = 0u;   // zeros: swizzle irrelevant
    }
    __syncthreads();

    const int yl = wid >> 1;             // local output row 0..3
    const int m0 = (wid & 1) * 64;       // 64 px per warp

    float acc[4][4][4];
    #pragma unroll
    for (int mi = 0; mi < 4; mi++)
        #pragma unroll
        for (int nt = 0; nt < 4; nt++)
            #pragma unroll
            for (int j = 0; j < 4; j++) acc[mi][nt][j] = 0.f;

    #pragma unroll
    for (int kh = 0; kh < 3; kh++) {
        const uint32_t* xr = sX + (yl + kh) * XROWW;
        #pragma unroll
        for (int kw = 0; kw < 3; kw++) {
            #pragma unroll
            for (int c16 = 0; c16 < 2; c16++) {
                const int k0w = kh * 48 + kw * 16 + c16 * 8;   // k word offset (for B)
                const int w0  = c16 * 8 + t;                    // A word (pre-swizzle)

                // B fragments (scalar LDS, proven pattern)
                uint32_t b0[4], b1[4];
                const uint32_t* wp = sW + k0w + t;
                #pragma unroll
                for (int nt = 0; nt < 4; nt++) {
                    int f = nt * 8 + g;
                    b0[nt] = wp[f * WPITCH];
                    b1[nt] = wp[f * WPITCH + 4];
                }

                #pragma unroll
                for (int mi = 0; mi < 4; mi++) {
                    const int px  = m0 + mi * 16 + g + kw;
                    const int sw  = SWZ(px);                    // same for px+8
                    const uint32_t* ap = xr + px * XPITCH;
                    uint32_t a0 = ap[w0 ^ sw];
                    uint32_t a1 = ap[8 * XPITCH + (w0 ^ sw)];
                    uint32_t a2 = ap[(w0 + 4) ^ sw];
                    uint32_t a3 = ap[8 * XPITCH + ((w0 + 4) ^ sw)];
                    #pragma unroll
                    for (int nt = 0; nt < 4; nt++)
                        mma_f16(acc[mi][nt][0], acc[mi][nt][1],
                                acc[mi][nt][2], acc[mi][nt][3],
                                a0, a1, a2, a3, b0[nt], b1[nt]);
                }
            }
        }
    }

    // ---- epilogue: + bias, store ----
    const float* bp = params + (long)b * PSTRIDE + WSIZE;
    float* ob = out + ((long)(b * 128 + y0 + yl)) * 128 * 32;
    #pragma unroll
    for (int nt = 0; nt < 4; nt++) {
        int f = nt * 8 + t * 2;
        float2 bias = *(const float2*)(bp + f);
        #pragma unroll
        for (int mi = 0; mi < 4; mi++) {
            int px = m0 + mi * 16 + g;
            float2 o0, o1;
            o0.x = acc[mi][nt][0] + bias.x;
            o0.y = acc[mi][nt][1] + bias.y;
            o1.x = acc[mi][nt][2] + bias.x;
            o1.y = acc[mi][nt][3] + bias.y;
            *(float2*)(ob + px * 32 + f)       = o0;
            *(float2*)(ob + (px + 8) * 32 + f) = o1;
        }
    }
}

extern "C" void kernel_launch(void* const* d_in, const int* in_sizes, int n_in,
                              void* d_out, int out_size) {
    const float* x      = (const float*)d_in[0];
    const float* params = (const float*)d_in[1];
    float* out          = (float*)d_out;

    wprep<<<96, 256>>>(params);

    cudaFuncSetAttribute(conv_mma_f16, cudaFuncAttributeMaxDynamicSharedMemorySize, SMEM_BYTES);
    dim3 grid(32, 32);   // (row-quad, batch)
    conv_mma_f16<<<grid, 256, SMEM_BYTES>>>(x, params, out);
}

// round 10
// speedup vs baseline: 1.5931x; 1.4884x over previous
#include <cuda_runtime.h>
#include <cuda_fp16.h>
#include <cstdint>

#define WSIZE 9216
#define PSTRIDE 9248

#define XPITCH 20                        // words/pixel: 16 data + 4 pad (conflict-free, proven R5)
#define XROWW  (130 * XPITCH)            // 2600
#define XT_WORDS (6 * XROWW)             // 15600
#define WPITCH 148                       // words/filter: 144 data + 4 pad (proven R5)
#define WT_WORDS (32 * WPITCH)           // 4736
#define EPITCH 37                        // epilogue stage pitch: 37 % 32 == 5 -> conflict-free
#define E_WORDS (16 * EPITCH)            // 592 words per warp
#define SE_OFF  (XT_WORDS + WT_WORDS)    // 20336
#define SMEM_BYTES ((SE_OFF + 8 * E_WORDS) * 4)   // 100288 -> 2 CTAs/SM

// precomputed W^T fp16, plain k-major: [b][f][WPITCH words], word w = (k=2w,2w+1)
__device__ uint32_t gWT[32 * WT_WORDS];

__device__ __forceinline__ uint32_t pack2(float a, float b) {
    __half2 h = __floats2half2_rn(a, b);
    return *(uint32_t*)&h;
}
__device__ __forceinline__ void mma_f16(float& c0, float& c1, float& c2, float& c3,
                                        uint32_t a0, uint32_t a1, uint32_t a2, uint32_t a3,
                                        uint32_t b0, uint32_t b1) {
    asm volatile(
        "mma.sync.aligned.m16n8k16.row.col.f32.f16.f16.f32 "
        "{%0,%1,%2,%3}, {%4,%5,%6,%7}, {%8,%9}, {%0,%1,%2,%3};"
        : "+f"(c0), "+f"(c1), "+f"(c2), "+f"(c3)
        : "r"(a0), "r"(a1), "r"(a2), "r"(a3), "r"(b0), "r"(b1));
}

// ---- precompute W^T fp16 (plain k-major), 9 small blocks per batch ----
__global__ __launch_bounds__(256)
void wprep(const float* __restrict__ params) {
    __shared__ float s[32 * 33];
    const int b  = blockIdx.x / 9;
    const int kc = blockIdx.x % 9;       // k chunk [kc*32, kc*32+32)
    const int tid = threadIdx.x;
    const float* pw = params + (long)b * PSTRIDE + kc * 1024;
    #pragma unroll
    for (int i = tid; i < 1024; i += 256) {
        int k = i >> 5, f = i & 31;
        s[k * 33 + f] = pw[i];
    }
    __syncthreads();
    uint32_t* gw = gWT + b * WT_WORDS + kc * 16;
    #pragma unroll
    for (int i = tid; i < 512; i += 256) {
        int f = i >> 4, n = i & 15;
        gw[f * WPITCH + n] = pack2(s[(2 * n) * 33 + f], s[(2 * n + 1) * 33 + f]);
    }
}

__global__ __launch_bounds__(256, 2)
void conv_mma_f16(const float* __restrict__ x, const float* __restrict__ params,
                  float* __restrict__ out) {
    extern __shared__ uint32_t smem[];
    uint32_t* sX = smem;                 // [row 0..5][pix 0..129][XPITCH], fp16 k-major
    uint32_t* sW = smem + XT_WORDS;      // [f][WPITCH], fp16 k-major

    const int tid = threadIdx.x;
    const int wid = tid >> 5;
    const int lid = tid & 31;
    const int g   = lid >> 2;
    const int t   = lid & 3;
    const int y0  = blockIdx.x * 4;      // 4 output rows per CTA
    const int b   = blockIdx.y;

    // ---- copy precomputed W^T (uint4 memcpy) ----
    const uint4* gw4 = (const uint4*)(gWT + b * WT_WORDS);
    #pragma unroll
    for (int it = 0; it < 5; it++) {
        int idx = tid + it * 256;
        if (idx < WT_WORDS / 4) ((uint4*)sW)[idx] = gw4[idx];
    }

    // ---- build X tile: input rows y0-1 .. y0+4, pixels -1..128 at 0..129 ----
    const float* xb = x + (long)b * (128 * 128 * 32);
    #pragma unroll
    for (int it = 0; it < 24; it++) {
        int idx = tid + it * 256;        // 0..6143
        int c4  = idx & 7;
        int px  = (idx >> 3) & 127;
        int row = idx >> 10;             // 0..5
        int gy  = y0 + row - 1;
        uint2 v = make_uint2(0u, 0u);
        if ((unsigned)gy < 128u) {
            float4 s = *(const float4*)(xb + ((gy * 128 + px) * 32 + c4 * 4));
            v.x = pack2(s.x, s.y);
            v.y = pack2(s.z, s.w);
        }
        *(uint2*)(sX + row * XROWW + (px + 1) * XPITCH + c4 * 2) = v;
    }
    if (tid < 192) {
        int row = tid >> 5, rem = tid & 31;
        int pix = (rem >> 4) ? 129 : 0;
        sX[row * XROWW + pix * XPITCH + (rem & 15)] = 0u;
    }
    __syncthreads();

    const int yl = wid >> 1;             // local output row 0..3
    const int m0 = (wid & 1) * 64;       // 64 px per warp

    float acc[4][4][4];
    #pragma unroll
    for (int mi = 0; mi < 4; mi++)
        #pragma unroll
        for (int nt = 0; nt < 4; nt++)
            #pragma unroll
            for (int j = 0; j < 4; j++) acc[mi][nt][j] = 0.f;

    #pragma unroll
    for (int kh = 0; kh < 3; kh++) {
        const uint32_t* xr = sX + (yl + kh) * XROWW;
        #pragma unroll
        for (int kw = 0; kw < 3; kw++) {
            #pragma unroll
            for (int c16 = 0; c16 < 2; c16++) {
                const int k0w = kh * 48 + kw * 16 + c16 * 8;

                // B fragments (scalar LDS, proven conflict-free)
                uint32_t b0[4], b1[4];
                const uint32_t* wp = sW + k0w + t;
                #pragma unroll
                for (int nt = 0; nt < 4; nt++) {
                    int f = nt * 8 + g;
                    b0[nt] = wp[f * WPITCH];
                    b1[nt] = wp[f * WPITCH + 4];
                }

                #pragma unroll
                for (int mi = 0; mi < 4; mi++) {
                    const uint32_t* ap = xr + (m0 + mi * 16 + g + kw) * XPITCH
                                            + c16 * 8 + t;
                    uint32_t a0 = ap[0];
                    uint32_t a1 = ap[8 * XPITCH];
                    uint32_t a2 = ap[4];
                    uint32_t a3 = ap[8 * XPITCH + 4];
                    #pragma unroll
                    for (int nt = 0; nt < 4; nt++)
                        mma_f16(acc[mi][nt][0], acc[mi][nt][1],
                                acc[mi][nt][2], acc[mi][nt][3],
                                a0, a1, a2, a3, b0[nt], b1[nt]);
                }
            }
        }
    }

    // ---- epilogue: stage through smem (pitch 37, conflict-free), coalesced STG.128 ----
    const float* bp = params + (long)b * PSTRIDE + WSIZE;
    float* sE = (float*)(smem + SE_OFF) + wid * E_WORDS;   // private per warp
    float* ob = out + ((long)(b * 128 + y0 + yl)) * 128 * 32;

    #pragma unroll
    for (int mi = 0; mi < 4; mi++) {
        __syncwarp();                    // previous round's reads complete
        #pragma unroll
        for (int nt = 0; nt < 4; nt++) {
            const int fw = nt * 8 + 2 * t;
            float2 bias = *(const float2*)(bp + fw);
            sE[g * EPITCH + fw]           = acc[mi][nt][0] + bias.x;
            sE[g * EPITCH + fw + 1]       = acc[mi][nt][1] + bias.y;
            sE[(g + 8) * EPITCH + fw]     = acc[mi][nt][2] + bias.x;
            sE[(g + 8) * EPITCH + fw + 1] = acc[mi][nt][3] + bias.y;
        }
        __syncwarp();
        #pragma unroll
        for (int r = 0; r < 4; r++) {
            const int p  = r * 4 + (lid >> 3);
            const int q4 = (lid & 7) * 4;
            float4 o;
            o.x = sE[p * EPITCH + q4 + 0];
            o.y = sE[p * EPITCH + q4 + 1];
            o.z = sE[p * EPITCH + q4 + 2];
            o.w = sE[p * EPITCH + q4 + 3];
            *(float4*)(ob + (m0 + mi * 16 + p) * 32 + q4) = o;
        }
    }
}

extern "C" void kernel_launch(void* const* d_in, const int* in_sizes, int n_in,
                              void* d_out, int out_size) {
    const float* x      = (const float*)d_in[0];
    const float* params = (const float*)d_in[1];
    float* out          = (float*)d_out;

    wprep<<<288, 256>>>(params);

    cudaFuncSetAttribute(conv_mma_f16, cudaFuncAttributeMaxDynamicSharedMemorySize, SMEM_BYTES);
    dim3 grid(32, 32);   // (row-quad, batch)
    conv_mma_f16<<<grid, 256, SMEM_BYTES>>>(x, params, out);
}

// round 11
// speedup vs baseline: 1.9259x; 1.2089x over previous
#include <cuda_runtime.h>
#include <cuda_fp16.h>
#include <cstdint>

#define WSIZE 9216
#define PSTRIDE 9248

#define XPITCH 20                        // words/pixel: 16 data + 4 pad (conflict-free, proven R5)
#define XROWW  (130 * XPITCH)            // 2600
#define XT_WORDS (6 * XROWW)             // 15600
#define WPITCH 148                       // words/filter: 144 data + 4 pad (proven R5)
#define WT_WORDS (32 * WPITCH)           // 4736
#define SMEM_BYTES ((XT_WORDS + WT_WORDS) * 4)   // 81344 -> 2 CTAs/SM (smem), 32 warps/SM

// precomputed W^T fp16, plain k-major: [b][f][WPITCH words], word w = (k=2w,2w+1)
__device__ uint32_t gWT[32 * WT_WORDS];

__device__ __forceinline__ uint32_t pack2(float a, float b) {
    __half2 h = __floats2half2_rn(a, b);
    return *(uint32_t*)&h;
}
__device__ __forceinline__ void mma_f16(float& c0, float& c1, float& c2, float& c3,
                                        uint32_t a0, uint32_t a1, uint32_t a2, uint32_t a3,
                                        uint32_t b0, uint32_t b1) {
    asm volatile(
        "mma.sync.aligned.m16n8k16.row.col.f32.f16.f16.f32 "
        "{%0,%1,%2,%3}, {%4,%5,%6,%7}, {%8,%9}, {%0,%1,%2,%3};"
        : "+f"(c0), "+f"(c1), "+f"(c2), "+f"(c3)
        : "r"(a0), "r"(a1), "r"(a2), "r"(a3), "r"(b0), "r"(b1));
}

// ---- precompute W^T fp16 (plain k-major), 9 small blocks per batch ----
__global__ __launch_bounds__(256)
void wprep(const float* __restrict__ params) {
    __shared__ float s[32 * 33];
    const int b  = blockIdx.x / 9;
    const int kc = blockIdx.x % 9;
    const int tid = threadIdx.x;
    const float* pw = params + (long)b * PSTRIDE + kc * 1024;
    #pragma unroll
    for (int i = tid; i < 1024; i += 256) {
        int k = i >> 5, f = i & 31;
        s[k * 33 + f] = pw[i];
    }
    __syncthreads();
    uint32_t* gw = gWT + b * WT_WORDS + kc * 16;
    #pragma unroll
    for (int i = tid; i < 512; i += 256) {
        int f = i >> 4, n = i & 15;
        gw[f * WPITCH + n] = pack2(s[(2 * n) * 33 + f], s[(2 * n + 1) * 33 + f]);
    }
}

__global__ __launch_bounds__(512, 2)
void conv_mma_f16(const float* __restrict__ x, const float* __restrict__ params,
                  float* __restrict__ out) {
    extern __shared__ uint32_t smem[];
    uint32_t* sX = smem;                 // [row 0..5][pix 0..129][XPITCH], fp16 k-major
    uint32_t* sW = smem + XT_WORDS;      // [f][WPITCH], fp16 k-major

    const int tid = threadIdx.x;
    const int wid = tid >> 5;            // 0..15
    const int lid = tid & 31;
    const int g   = lid >> 2;
    const int t   = lid & 3;
    const int y0  = blockIdx.x * 4;      // 4 output rows per CTA
    const int b   = blockIdx.y;

    // ---- copy precomputed W^T (uint4 memcpy) ----
    const uint4* gw4 = (const uint4*)(gWT + b * WT_WORDS);
    #pragma unroll
    for (int it = 0; it < 3; it++) {
        int idx = tid + it * 512;
        if (idx < WT_WORDS / 4) ((uint4*)sW)[idx] = gw4[idx];
    }

    // ---- build X tile: input rows y0-1 .. y0+4, pixels -1..128 at 0..129 ----
    const float* xb = x + (long)b * (128 * 128 * 32);
    #pragma unroll
    for (int it = 0; it < 12; it++) {
        int idx = tid + it * 512;        // 0..6143
        int c4  = idx & 7;
        int px  = (idx >> 3) & 127;
        int row = idx >> 10;             // 0..5
        int gy  = y0 + row - 1;
        uint2 v = make_uint2(0u, 0u);
        if ((unsigned)gy < 128u) {
            float4 s = *(const float4*)(xb + ((gy * 128 + px) * 32 + c4 * 4));
            v.x = pack2(s.x, s.y);
            v.y = pack2(s.z, s.w);
        }
        *(uint2*)(sX + row * XROWW + (px + 1) * XPITCH + c4 * 2) = v;
    }
    if (tid < 192) {
        int row = tid >> 5, rem = tid & 31;
        int pix = (rem >> 4) ? 129 : 0;
        sX[row * XROWW + pix * XPITCH + (rem & 15)] = 0u;
    }
    __syncthreads();

    const int yl = wid >> 2;             // local output row 0..3
    const int m0 = (wid & 3) * 32;       // 32 px per warp

    float acc[2][4][4];
    #pragma unroll
    for (int mi = 0; mi < 2; mi++)
        #pragma unroll
        for (int nt = 0; nt < 4; nt++)
            #pragma unroll
            for (int j = 0; j < 4; j++) acc[mi][nt][j] = 0.f;

    #pragma unroll
    for (int kh = 0; kh < 3; kh++) {
        const uint32_t* xr = sX + (yl + kh) * XROWW;
        #pragma unroll
        for (int kw = 0; kw < 3; kw++) {
            #pragma unroll
            for (int c16 = 0; c16 < 2; c16++) {
                const int k0w = kh * 48 + kw * 16 + c16 * 8;

                // B fragments (scalar LDS, proven conflict-free)
                uint32_t b0[4], b1[4];
                const uint32_t* wp = sW + k0w + t;
                #pragma unroll
                for (int nt = 0; nt < 4; nt++) {
                    int f = nt * 8 + g;
                    b0[nt] = wp[f * WPITCH];
                    b1[nt] = wp[f * WPITCH + 4];
                }

                #pragma unroll
                for (int mi = 0; mi < 2; mi++) {
                    const uint32_t* ap = xr + (m0 + mi * 16 + g + kw) * XPITCH
                                            + c16 * 8 + t;
                    uint32_t a0 = ap[0];
                    uint32_t a1 = ap[8 * XPITCH];
                    uint32_t a2 = ap[4];
                    uint32_t a3 = ap[8 * XPITCH + 4];
                    #pragma unroll
                    for (int nt = 0; nt < 4; nt++)
                        mma_f16(acc[mi][nt][0], acc[mi][nt][1],
                                acc[mi][nt][2], acc[mi][nt][3],
                                a0, a1, a2, a3, b0[nt], b1[nt]);
                }
            }
        }
    }

    // ---- epilogue: + bias, direct STG (R5-proven) ----
    const float* bp = params + (long)b * PSTRIDE + WSIZE;
    float* ob = out + ((long)(b * 128 + y0 + yl)) * 128 * 32;
    #pragma unroll
    for (int nt = 0; nt < 4; nt++) {
        int f = nt * 8 + t * 2;
        float2 bias = *(const float2*)(bp + f);
        #pragma unroll
        for (int mi = 0; mi < 2; mi++) {
            int px = m0 + mi * 16 + g;
            float2 o0, o1;
            o0.x = acc[mi][nt][0] + bias.x;
            o0.y = acc[mi][nt][1] + bias.y;
            o1.x = acc[mi][nt][2] + bias.x;
            o1.y = acc[mi][nt][3] + bias.y;
            *(float2*)(ob + px * 32 + f)       = o0;
            *(float2*)(ob + (px + 8) * 32 + f) = o1;
        }
    }
}

extern "C" void kernel_launch(void* const* d_in, const int* in_sizes, int n_in,
                              void* d_out, int out_size) {
    const float* x      = (const float*)d_in[0];
    const float* params = (const float*)d_in[1];
    float* out          = (float*)d_out;

    wprep<<<288, 256>>>(params);

    cudaFuncSetAttribute(conv_mma_f16, cudaFuncAttributeMaxDynamicSharedMemorySize, SMEM_BYTES);
    dim3 grid(32, 32);   // (row-quad, batch)
    conv_mma_f16<<<grid, 512, SMEM_BYTES>>>(x, params, out);
}